// round 9
// baseline (speedup 1.0000x reference)
#include <cuda_runtime.h>
#include <cstdint>

#define HH 128
#define WW 128
#define BB 8
#define NPAIR 16          // 16 pairs; pair = 64 k-values (2 chunks of 32)

// ---- smem byte layout (per CTA) ----
#define AB_OFF 0                      // 2 x 36864 : A pair [2 chunk][128 m][36 w] (stride 144B)
#define AB_SZ  36864
#define YB_OFF 73728                  // 2 x 17408 : Y pair [64 k][68 w] (stride 272B)
#define YB_SZ  17408
#define SMEM_BYTES 108544

// wproj pre-converted to tf32: [chunk(32)][m(256)][k(32)] u32
__device__ uint32_t g_A_tf32[32 * 256 * 32];
// depthwise weights packed: [ch(256)][conv(4: h1,h2,v1,v2)][12 floats (9 + pad)]
__device__ float g_dw[256 * 4 * 12];

// ================= helpers =================
__device__ __forceinline__ uint32_t smem_u32(const void* p) {
    uint32_t a;
    asm("{ .reg .u64 t; cvta.to.shared.u64 t, %1; cvt.u32.u64 %0, t; }" : "=r"(a) : "l"(p));
    return a;
}
__device__ __forceinline__ void cpa16(uint32_t dst, const void* src) {
    unsigned long long g = (unsigned long long)__cvta_generic_to_global((void*)src);
    asm volatile("cp.async.cg.shared.global [%0], [%1], 16;" :: "r"(dst), "l"(g));
}
__device__ __forceinline__ uint32_t f2tf32(float v) {
    uint32_t u;
    asm("cvt.rna.tf32.f32 %0, %1;" : "=r"(u) : "f"(v));
    return u;
}
__device__ __forceinline__ void ldsm4(uint32_t* r, uint32_t addr) {
    asm volatile("ldmatrix.sync.aligned.m8n8.x4.shared.b16 {%0,%1,%2,%3}, [%4];"
        : "=r"(r[0]), "=r"(r[1]), "=r"(r[2]), "=r"(r[3]) : "r"(addr));
}
__device__ __forceinline__ void mma_tf32(float* d, const uint32_t* a, const uint32_t* b) {
    asm volatile("mma.sync.aligned.m16n8k8.row.col.f32.tf32.tf32.f32 "
        "{%0,%1,%2,%3}, {%4,%5,%6,%7}, {%8,%9}, {%0,%1,%2,%3};"
        : "+f"(d[0]), "+f"(d[1]), "+f"(d[2]), "+f"(d[3])
        : "r"(a[0]), "r"(a[1]), "r"(a[2]), "r"(a[3]), "r"(b[0]), "r"(b[1]));
}

// ================= prep: wproj -> tf32, dw weights -> packed =================
__global__ void se_prep(const float* __restrict__ wproj,
                        const float* __restrict__ wh1, const float* __restrict__ wh2,
                        const float* __restrict__ wv1, const float* __restrict__ wv2)
{
    int idx = blockIdx.x * 256 + threadIdx.x;   // 262144
    int k = idx & 31;
    int m = (idx >> 5) & 255;
    int c = idx >> 13;
    int br = k >> 3, lc = k & 7;
    float v = wproj[m * 1024 + br * 256 + c * 8 + lc];
    g_A_tf32[(c * 256 + m) * 32 + k] = f2tf32(v);

    if (blockIdx.x == 0) {
        for (int i = threadIdx.x; i < 9216; i += 256) {
            int ch = i / 36, r = i - ch * 36;
            int conv = r / 9, kk = r - conv * 9;
            const float* p = (conv == 0) ? wh1 : (conv == 1) ? wh2 : (conv == 2) ? wv1 : wv2;
            g_dw[(ch * 4 + conv) * 12 + kk] = p[ch * 9 + kk];
        }
    }
}

// ================= main =================
// grid (4, HH, BB): blockIdx.x = mh + 2*half  (mh = M-half, half = N-half)
__global__ __launch_bounds__(256, 2)
void se_main(const float* __restrict__ x, float* __restrict__ out)
{
    extern __shared__ char smc[];
    const uint32_t sb = smem_u32(smc);
    const int mh = blockIdx.x & 1, half = blockIdx.x >> 1;
    const int h = blockIdx.y, b = blockIdx.z;
    const int t = threadIdx.x, lane = t & 31, wid = t >> 5;
    const int wm = (wid & 1) * 64;       // M tile base within 128-half
    const int wn = (wid >> 1) * 16;      // N tile base within 64-px half

    // depthwise mapping: 16 pixel-groups x 16 channels (one pair = 2 chunks)
    const int ng = t & 15, ch = t >> 4;           // ch 0..15
    const int cs = ch >> 3, lch = ch & 7;         // chunk-within-pair, local channel
    const int p0 = half * 64 + ng * 4;            // global pixel base (4 px)
    const int n0 = ng * 4;                        // local pixel base

    const float* xb = x + (long)b * 256 * HH * WW;

    // ---- A prefetch: pair p (2 chunks x 128 m rows) -> smem buffer dbuf ----
    auto pa = [&](int p, int dbuf) {
        #pragma unroll
        for (int i = 0; i < 8; ++i) {
            int idx = t + i * 256;               // 0..2047
            int cs2 = idx >> 10, rem = idx & 1023;
            int m = rem >> 3, q = rem & 7;
            cpa16(sb + AB_OFF + (uint32_t)(dbuf * AB_SZ + cs2 * 18432 + m * 144 + q * 16),
                  &g_A_tf32[((2 * p + cs2) * 256 + mh * 128 + m) * 32 + q * 4]);
        }
    };

    // ---- depthwise: pair pr (all 4 convs of this thread's channel) -> Y[ybuf] ----
    auto dw = [&](int pr, int ybuf) {
        uint32_t* Yw = (uint32_t*)(smc + YB_OFF + ybuf * YB_SZ);
        const int gch = (2 * pr + cs) * 8 + lch;
        const float* xch = xb + (long)gch * HH * WW;
        const float* xr = xch + h * WW;
        const float4 Z4 = make_float4(0.f, 0.f, 0.f, 0.f);

        // row-h neighborhood (shared by H convs and V center tap)
        float4 xh0 = (p0 >= 4)      ? *(const float4*)(xr + p0 - 4) : Z4;
        float4 xh1 =                  *(const float4*)(xr + p0);
        float4 xh2 = (p0 + 7 < 128) ? *(const float4*)(xr + p0 + 4) : Z4;

        // ---- horizontal convs (wh1, wh2) ----
        {
            const float* wp = g_dw + (gch * 4 + 0) * 12;
            float xv[12];
            xv[0] = xh0.x; xv[1] = xh0.y; xv[2]  = xh0.z; xv[3]  = xh0.w;
            xv[4] = xh1.x; xv[5] = xh1.y; xv[6]  = xh1.z; xv[7]  = xh1.w;
            xv[8] = xh2.x; xv[9] = xh2.y; xv[10] = xh2.z; xv[11] = xh2.w;
            float a0 = 0.f, a1 = 0.f, a2 = 0.f, a3 = 0.f;
            float b0 = 0.f, b1 = 0.f, b2 = 0.f, b3 = 0.f;
            #pragma unroll
            for (int k = 0; k < 9; ++k) {
                const float wa = wp[k], wb2 = wp[12 + k];
                a0 = fmaf(wa, xv[k],     a0); b0 = fmaf(wb2, xv[k],     b0);
                a1 = fmaf(wa, xv[k + 1], a1); b1 = fmaf(wb2, xv[k + 1], b1);
                a2 = fmaf(wa, xv[k + 2], a2); b2 = fmaf(wb2, xv[k + 2], b2);
                a3 = fmaf(wa, xv[k + 3], a3); b3 = fmaf(wb2, xv[k + 3], b3);
            }
            uint4 s0, s1;
            s0.x = f2tf32(a0); s0.y = f2tf32(a1); s0.z = f2tf32(a2); s0.w = f2tf32(a3);
            s1.x = f2tf32(b0); s1.y = f2tf32(b1); s1.z = f2tf32(b2); s1.w = f2tf32(b3);
            *(uint4*)(Yw + (cs * 32 + lch) * 68 + n0)     = s0;
            *(uint4*)(Yw + (cs * 32 + 8 + lch) * 68 + n0) = s1;
        }

        // ---- vertical convs (wv1, wv2) ----
        {
            const float* wp = g_dw + (gch * 4 + 2) * 12;
            float a0 = 0.f, a1 = 0.f, a2 = 0.f, a3 = 0.f;
            float b0 = 0.f, b1 = 0.f, b2 = 0.f, b3 = 0.f;
            #pragma unroll
            for (int r = 0; r < 9; ++r) {
                const int hh = h + r - 4;
                float4 v;
                if (r == 4)                    v = xh1;
                else if ((unsigned)hh < 128u)  v = *(const float4*)(xch + hh * WW + p0);
                else                           v = Z4;
                const float wa = wp[r], wb2 = wp[12 + r];
                a0 = fmaf(wa, v.x, a0); b0 = fmaf(wb2, v.x, b0);
                a1 = fmaf(wa, v.y, a1); b1 = fmaf(wb2, v.y, b1);
                a2 = fmaf(wa, v.z, a2); b2 = fmaf(wb2, v.z, b2);
                a3 = fmaf(wa, v.w, a3); b3 = fmaf(wb2, v.w, b3);
            }
            uint4 s0, s1;
            s0.x = f2tf32(a0); s0.y = f2tf32(a1); s0.z = f2tf32(a2); s0.w = f2tf32(a3);
            s1.x = f2tf32(b0); s1.y = f2tf32(b1); s1.z = f2tf32(b2); s1.w = f2tf32(b3);
            *(uint4*)(Yw + (cs * 32 + 16 + lch) * 68 + n0) = s0;
            *(uint4*)(Yw + (cs * 32 + 24 + lch) * 68 + n0) = s1;
        }
    };

    // ---- prologue: A(pair 0) + dw(pair 0) ----
    pa(0, 0);
    asm volatile("cp.async.commit_group;" ::: "memory");
    dw(0, 0);
    asm volatile("cp.async.wait_group 0;" ::: "memory");
    __syncthreads();

    float acc[4][2][4];
    #pragma unroll
    for (int i = 0; i < 4; ++i)
        #pragma unroll
        for (int j = 0; j < 2; ++j)
            #pragma unroll
            for (int e = 0; e < 4; ++e) acc[i][j][e] = 0.f;

    const int fr = lane >> 2, fq = lane & 3;
    const uint32_t aLane = (uint32_t)(((lane & 7) + ((lane >> 3) & 1) * 8) * 144 + ((lane >> 4) << 4));

    // ---- main loop: one barrier per PAIR (64 k per window) ----
    for (int p = 0; p < NPAIR; ++p) {
        const int buf = p & 1;
        if (p + 1 < NPAIR) {
            pa(p + 1, buf ^ 1);
            asm volatile("cp.async.commit_group;" ::: "memory");
            dw(p + 1, buf ^ 1);
        }

        {   // MMA pair p: K=64 in 8 ksteps of 8; A via ldmatrix, B scalar
            const uint32_t abase = sb + AB_OFF + (uint32_t)(buf * AB_SZ) + (uint32_t)(wm * 144) + aLane;
            const uint32_t* Yp = (const uint32_t*)(smc + YB_OFF + buf * YB_SZ);
            #pragma unroll
            for (int ks = 0; ks < 8; ++ks) {
                const uint32_t coff = (uint32_t)((ks >> 2) * 18432 + (ks & 3) * 32);
                uint32_t a[4][4];
                #pragma unroll
                for (int mt = 0; mt < 4; ++mt)
                    ldsm4(a[mt], abase + coff + (uint32_t)(mt * 16 * 144));
                uint32_t bf[2][2];
                #pragma unroll
                for (int nt = 0; nt < 2; ++nt) {
                    const int col = wn + nt * 8 + fr;
                    bf[nt][0] = Yp[(ks * 8 + fq) * 68 + col];
                    bf[nt][1] = Yp[(ks * 8 + fq + 4) * 68 + col];
                }
                #pragma unroll
                for (int mt = 0; mt < 4; ++mt)
                    #pragma unroll
                    for (int nt = 0; nt < 2; ++nt)
                        mma_tf32(acc[mt][nt], a[mt], &bf[nt][0]);
            }
        }

        asm volatile("cp.async.wait_group 0;" ::: "memory");
        __syncthreads();
    }

    // ---- epilogue: ReLU + store (D fragment layout) ----
    const int g2 = lane >> 2, cq = lane & 3;
    #pragma unroll
    for (int mt = 0; mt < 4; ++mt) {
        const int o0 = mh * 128 + wm + mt * 16 + g2;
        #pragma unroll
        for (int nt = 0; nt < 2; ++nt) {
            const int nn0 = half * 64 + wn + nt * 8 + cq * 2;
            float* p = out + (((long)(b * 256 + o0)) * HH + h) * WW + nn0;
            float2 v0, v1;
            v0.x = fmaxf(acc[mt][nt][0], 0.f);
            v0.y = fmaxf(acc[mt][nt][1], 0.f);
            v1.x = fmaxf(acc[mt][nt][2], 0.f);
            v1.y = fmaxf(acc[mt][nt][3], 0.f);
            *(float2*)p = v0;
            *(float2*)(p + 8L * HH * WW) = v1;
        }
    }
}

// ================= launch =================
extern "C" void kernel_launch(void* const* d_in, const int* in_sizes, int n_in,
                              void* d_out, int out_size)
{
    const float* x     = (const float*)d_in[0];
    const float* wh1   = (const float*)d_in[1];
    const float* wh2   = (const float*)d_in[2];
    const float* wv1   = (const float*)d_in[3];
    const float* wv2   = (const float*)d_in[4];
    const float* wproj = (const float*)d_in[5];
    float* out = (float*)d_out;

    se_prep<<<1024, 256>>>(wproj, wh1, wh2, wv1, wv2);

    cudaFuncSetAttribute(se_main, cudaFuncAttributeMaxDynamicSharedMemorySize, SMEM_BYTES);
    dim3 grid(4, HH, BB);
    se_main<<<grid, 256, SMEM_BYTES>>>(x, out);
}

// round 10
// speedup vs baseline: 1.3727x; 1.3727x over previous
#include <cuda_runtime.h>
#include <cstdint>

#define HH 128
#define WW 128
#define BB 8
#define NCH 32            // 32 k-chunks; chunk = 8 input channels x 4 branches = 32 y-channels
#define NSTG 3            // pipeline stages

// ---- smem byte layout (per CTA) ----
#define AB_OFF 0                      // 3 x 36864 : A stage [256 m][36 w] (stride 144B)
#define AB_SZ  36864
#define YB_OFF 110592                 // 3 x 8704  : Y stage [32 k][68 w] (stride 272B)
#define YB_SZ  8704
#define SMEM_BYTES 136704

// named barrier ids
#define BFULL(s)  (1 + (s))
#define BEMPTY(s) (4 + (s))

// wproj pre-converted to tf32: [chunk(32)][m(256)][k(32)] u32
__device__ uint32_t g_A_tf32[32 * 256 * 32];
// depthwise weights packed: [ch(256)][conv(4: h1,h2,v1,v2)][12 floats (9 + pad)]
__device__ float g_dw[256 * 4 * 12];

// ================= helpers =================
__device__ __forceinline__ uint32_t smem_u32(const void* p) {
    uint32_t a;
    asm("{ .reg .u64 t; cvta.to.shared.u64 t, %1; cvt.u32.u64 %0, t; }" : "=r"(a) : "l"(p));
    return a;
}
__device__ __forceinline__ void cpa16(uint32_t dst, const void* src) {
    unsigned long long g = (unsigned long long)__cvta_generic_to_global((void*)src);
    asm volatile("cp.async.cg.shared.global [%0], [%1], 16;" :: "r"(dst), "l"(g));
}
__device__ __forceinline__ uint32_t f2tf32(float v) {
    uint32_t u;
    asm("cvt.rna.tf32.f32 %0, %1;" : "=r"(u) : "f"(v));
    return u;
}
__device__ __forceinline__ void ldsm4(uint32_t* r, uint32_t addr) {
    asm volatile("ldmatrix.sync.aligned.m8n8.x4.shared.b16 {%0,%1,%2,%3}, [%4];"
        : "=r"(r[0]), "=r"(r[1]), "=r"(r[2]), "=r"(r[3]) : "r"(addr));
}
__device__ __forceinline__ void mma_tf32(float* d, const uint32_t* a, const uint32_t* b) {
    asm volatile("mma.sync.aligned.m16n8k8.row.col.f32.tf32.tf32.f32 "
        "{%0,%1,%2,%3}, {%4,%5,%6,%7}, {%8,%9}, {%0,%1,%2,%3};"
        : "+f"(d[0]), "+f"(d[1]), "+f"(d[2]), "+f"(d[3])
        : "r"(a[0]), "r"(a[1]), "r"(a[2]), "r"(a[3]), "r"(b[0]), "r"(b[1]));
}
__device__ __forceinline__ void bar_sync(int id) {
    asm volatile("bar.sync %0, 384;" :: "r"(id) : "memory");
}
__device__ __forceinline__ void bar_arrive(int id) {
    asm volatile("bar.arrive %0, 384;" :: "r"(id) : "memory");
}

// ================= prep: wproj -> tf32, dw weights -> packed =================
__global__ void se_prep(const float* __restrict__ wproj,
                        const float* __restrict__ wh1, const float* __restrict__ wh2,
                        const float* __restrict__ wv1, const float* __restrict__ wv2)
{
    int idx = blockIdx.x * 256 + threadIdx.x;   // 262144
    int k = idx & 31;
    int m = (idx >> 5) & 255;
    int c = idx >> 13;
    int br = k >> 3, lc = k & 7;
    float v = wproj[m * 1024 + br * 256 + c * 8 + lc];
    g_A_tf32[(c * 256 + m) * 32 + k] = f2tf32(v);

    if (blockIdx.x == 0) {
        for (int i = threadIdx.x; i < 9216; i += 256) {
            int ch = i / 36, r = i - ch * 36;
            int conv = r / 9, kk = r - conv * 9;
            const float* p = (conv == 0) ? wh1 : (conv == 1) ? wh2 : (conv == 2) ? wv1 : wv2;
            g_dw[(ch * 4 + conv) * 12 + kk] = p[ch * 9 + kk];
        }
    }
}

// ================= main: warp-specialized producer/consumer =================
// grid (2, HH, BB): blockIdx.x = half (N-half of the row)
__global__ __launch_bounds__(384, 1)
void se_main(const float* __restrict__ x, float* __restrict__ out)
{
    extern __shared__ char smc[];
    const uint32_t sb = smem_u32(smc);
    const int half = blockIdx.x, h = blockIdx.y, b = blockIdx.z;
    const int t = threadIdx.x, lane = t & 31;

    const float* xb = x + (long)b * 256 * HH * WW;

    if (t < 256) {
        // ================== CONSUMERS: 8 warps, MMA only ==================
        const int wid = t >> 5;
        const int wm = (wid & 3) * 64;       // M tile base
        const int wn = (wid >> 2) * 32;      // N tile base within 64-px half
        const int fr = lane >> 2, fq = lane & 3;
        const uint32_t aLane = (uint32_t)(((lane & 7) + ((lane >> 3) & 1) * 8) * 144 + ((lane >> 4) << 4));

        float acc[4][4][4];
        #pragma unroll
        for (int i = 0; i < 4; ++i)
            #pragma unroll
            for (int j = 0; j < 4; ++j)
                #pragma unroll
                for (int e = 0; e < 4; ++e) acc[i][j][e] = 0.f;

        for (int c = 0; c < NCH; ++c) {
            const int s = c % NSTG;
            bar_sync(BFULL(s));

            const uint32_t abase = sb + AB_OFF + (uint32_t)(s * AB_SZ) + (uint32_t)(wm * 144) + aLane;
            const uint32_t* Yp = (const uint32_t*)(smc + YB_OFF + s * YB_SZ);
            #pragma unroll
            for (int ks = 0; ks < 4; ++ks) {
                const int k0 = ks * 8;
                uint32_t a[4][4];
                #pragma unroll
                for (int mt = 0; mt < 4; ++mt)
                    ldsm4(a[mt], abase + (uint32_t)(mt * 16 * 144 + k0 * 4));
                uint32_t bf[4][2];
                #pragma unroll
                for (int nt = 0; nt < 4; ++nt) {
                    const int col = wn + nt * 8 + fr;
                    bf[nt][0] = Yp[(k0 + fq) * 68 + col];
                    bf[nt][1] = Yp[(k0 + fq + 4) * 68 + col];
                }
                #pragma unroll
                for (int mt = 0; mt < 4; ++mt)
                    #pragma unroll
                    for (int nt = 0; nt < 4; ++nt)
                        mma_tf32(acc[mt][nt], a[mt], &bf[nt][0]);
            }

            if (c + NSTG < NCH) bar_arrive(BEMPTY(s));
        }

        // ---- epilogue: ReLU + store (D fragment layout) ----
        const int g2 = lane >> 2, cq = lane & 3;
        #pragma unroll
        for (int mt = 0; mt < 4; ++mt) {
            const int o0 = wm + mt * 16 + g2;
            #pragma unroll
            for (int nt = 0; nt < 4; ++nt) {
                const int nn0 = half * 64 + wn + nt * 8 + cq * 2;
                float* p = out + (((long)(b * 256 + o0)) * HH + h) * WW + nn0;
                float2 v0, v1;
                v0.x = fmaxf(acc[mt][nt][0], 0.f);
                v0.y = fmaxf(acc[mt][nt][1], 0.f);
                v1.x = fmaxf(acc[mt][nt][2], 0.f);
                v1.y = fmaxf(acc[mt][nt][3], 0.f);
                *(float2*)p = v0;
                *(float2*)(p + 8L * HH * WW) = v1;
            }
        }
    } else {
        // ================== PRODUCERS: 4 warps, dw + A staging ==================
        const int pt = t - 256;                   // 0..127
        const int ng = pt & 15, ch = pt >> 4;     // pixel group, channel 0..7
        const int p0 = half * 64 + ng * 4;        // global pixel base (4 px)
        const int n0 = ng * 4;                    // local pixel base
        const float4 Z4 = make_float4(0.f, 0.f, 0.f, 0.f);

        // x registers for the current chunk (row h neighborhood + 8 V rows)
        float4 xh0, xh1, xh2, xv[8];

        auto loadx = [&](int c) {
            const float* xch = xb + (long)(c * 8 + ch) * HH * WW;
            const float* xr = xch + h * WW;
            xh0 = (p0 >= 4)      ? *(const float4*)(xr + p0 - 4) : Z4;
            xh1 =                  *(const float4*)(xr + p0);
            xh2 = (p0 + 7 < 128) ? *(const float4*)(xr + p0 + 4) : Z4;
            #pragma unroll
            for (int r = 0; r < 9; ++r) {
                if (r == 4) continue;
                const int hh = h + r - 4;
                const int i = (r < 4) ? r : r - 1;
                xv[i] = ((unsigned)hh < 128u) ? *(const float4*)(xch + hh * WW + p0) : Z4;
            }
        };

        loadx(0);

        for (int c = 0; c < NCH; ++c) {
            const int s = c % NSTG;
            if (c >= NSTG) bar_sync(BEMPTY(s));

            // A stage: 2048 float4 / 128 threads = 16 each
            #pragma unroll
            for (int i = 0; i < 16; ++i) {
                const int idx = pt + i * 128;
                const int m = idx >> 3, q = idx & 7;
                cpa16(sb + AB_OFF + (uint32_t)(s * AB_SZ + m * 144 + q * 16),
                      &g_A_tf32[(c * 256 + m) * 32 + q * 4]);
            }
            asm volatile("cp.async.commit_group;" ::: "memory");

            // ---- depthwise for chunk c from preloaded regs ----
            const int gch = c * 8 + ch;
            const float* wp = g_dw + gch * 48;
            uint32_t* Yw = (uint32_t*)(smc + YB_OFF + s * YB_SZ);

            {   // horizontal convs (wh1 -> k=ch, wh2 -> k=8+ch)
                float xvv[12];
                xvv[0] = xh0.x; xvv[1] = xh0.y; xvv[2]  = xh0.z; xvv[3]  = xh0.w;
                xvv[4] = xh1.x; xvv[5] = xh1.y; xvv[6]  = xh1.z; xvv[7]  = xh1.w;
                xvv[8] = xh2.x; xvv[9] = xh2.y; xvv[10] = xh2.z; xvv[11] = xh2.w;
                float a0 = 0.f, a1 = 0.f, a2 = 0.f, a3 = 0.f;
                float b0 = 0.f, b1 = 0.f, b2 = 0.f, b3 = 0.f;
                #pragma unroll
                for (int k = 0; k < 9; ++k) {
                    const float wa = wp[k], wb2 = wp[12 + k];
                    a0 = fmaf(wa, xvv[k],     a0); b0 = fmaf(wb2, xvv[k],     b0);
                    a1 = fmaf(wa, xvv[k + 1], a1); b1 = fmaf(wb2, xvv[k + 1], b1);
                    a2 = fmaf(wa, xvv[k + 2], a2); b2 = fmaf(wb2, xvv[k + 2], b2);
                    a3 = fmaf(wa, xvv[k + 3], a3); b3 = fmaf(wb2, xvv[k + 3], b3);
                }
                uint4 s0, s1;
                s0.x = f2tf32(a0); s0.y = f2tf32(a1); s0.z = f2tf32(a2); s0.w = f2tf32(a3);
                s1.x = f2tf32(b0); s1.y = f2tf32(b1); s1.z = f2tf32(b2); s1.w = f2tf32(b3);
                *(uint4*)(Yw + (ch)     * 68 + n0) = s0;
                *(uint4*)(Yw + (8 + ch) * 68 + n0) = s1;
            }
            {   // vertical convs (wv1 -> k=16+ch, wv2 -> k=24+ch)
                const float* wq = wp + 24;
                float a0 = 0.f, a1 = 0.f, a2 = 0.f, a3 = 0.f;
                float b0 = 0.f, b1 = 0.f, b2 = 0.f, b3 = 0.f;
                #pragma unroll
                for (int r = 0; r < 9; ++r) {
                    const float4 v = (r == 4) ? xh1 : xv[(r < 4) ? r : r - 1];
                    const float wa = wq[r], wb2 = wq[12 + r];
                    a0 = fmaf(wa, v.x, a0); b0 = fmaf(wb2, v.x, b0);
                    a1 = fmaf(wa, v.y, a1); b1 = fmaf(wb2, v.y, b1);
                    a2 = fmaf(wa, v.z, a2); b2 = fmaf(wb2, v.z, b2);
                    a3 = fmaf(wa, v.w, a3); b3 = fmaf(wb2, v.w, b3);
                }
                uint4 s0, s1;
                s0.x = f2tf32(a0); s0.y = f2tf32(a1); s0.z = f2tf32(a2); s0.w = f2tf32(a3);
                s1.x = f2tf32(b0); s1.y = f2tf32(b1); s1.z = f2tf32(b2); s1.w = f2tf32(b3);
                *(uint4*)(Yw + (16 + ch) * 68 + n0) = s0;
                *(uint4*)(Yw + (24 + ch) * 68 + n0) = s1;
            }

            // start x loads for next chunk (latency hides under ring slack)
            if (c + 1 < NCH) loadx(c + 1);

            asm volatile("cp.async.wait_group 0;" ::: "memory");
            bar_arrive(BFULL(s));
        }
    }
}

// ================= launch =================
extern "C" void kernel_launch(void* const* d_in, const int* in_sizes, int n_in,
                              void* d_out, int out_size)
{
    const float* x     = (const float*)d_in[0];
    const float* wh1   = (const float*)d_in[1];
    const float* wh2   = (const float*)d_in[2];
    const float* wv1   = (const float*)d_in[3];
    const float* wv2   = (const float*)d_in[4];
    const float* wproj = (const float*)d_in[5];
    float* out = (float*)d_out;

    se_prep<<<1024, 256>>>(wproj, wh1, wh2, wv1, wv2);

    cudaFuncSetAttribute(se_main, cudaFuncAttributeMaxDynamicSharedMemorySize, SMEM_BYTES);
    dim3 grid(2, HH, BB);
    se_main<<<grid, 384, SMEM_BYTES>>>(x, out);
}

// round 11
// speedup vs baseline: 1.3824x; 1.0071x over previous
#include <cuda_runtime.h>
#include <cstdint>

#define HH 128
#define WW 128
#define BB 8
#define NCH 32            // 32 k-chunks; chunk = 8 input channels x 4 branches = 32 y-channels
#define NSTG 4            // pipeline stages

// ---- smem byte layout (per CTA) ----
#define AB_OFF 0                      // 4 x 36864 : A stage [256 m][36 w] (stride 144B)
#define AB_SZ  36864
#define YB_OFF 147456                 // 4 x 8704  : Y stage [32 k][68 w] (stride 272B)
#define YB_SZ  8704
#define SMEM_BYTES 182272

// named barrier ids
#define BFULL(s)  (1 + (s))
#define BEMPTY(s) (5 + (s))

// wproj pre-converted to tf32: [chunk(32)][m(256)][k(32)] u32
__device__ uint32_t g_A_tf32[32 * 256 * 32];
// depthwise weights packed: [ch(256)][conv(4: h1,h2,v1,v2)][12 floats (9 + pad)]
__device__ float g_dw[256 * 4 * 12];

// ================= helpers =================
__device__ __forceinline__ uint32_t smem_u32(const void* p) {
    uint32_t a;
    asm("{ .reg .u64 t; cvta.to.shared.u64 t, %1; cvt.u32.u64 %0, t; }" : "=r"(a) : "l"(p));
    return a;
}
__device__ __forceinline__ void cpa16(uint32_t dst, const void* src) {
    unsigned long long g = (unsigned long long)__cvta_generic_to_global((void*)src);
    asm volatile("cp.async.cg.shared.global [%0], [%1], 16;" :: "r"(dst), "l"(g));
}
__device__ __forceinline__ uint32_t f2tf32(float v) {
    uint32_t u;
    asm("cvt.rna.tf32.f32 %0, %1;" : "=r"(u) : "f"(v));
    return u;
}
__device__ __forceinline__ void ldsm4(uint32_t* r, uint32_t addr) {
    asm volatile("ldmatrix.sync.aligned.m8n8.x4.shared.b16 {%0,%1,%2,%3}, [%4];"
        : "=r"(r[0]), "=r"(r[1]), "=r"(r[2]), "=r"(r[3]) : "r"(addr));
}
__device__ __forceinline__ void mma_tf32(float* d, const uint32_t* a, const uint32_t* b) {
    asm volatile("mma.sync.aligned.m16n8k8.row.col.f32.tf32.tf32.f32 "
        "{%0,%1,%2,%3}, {%4,%5,%6,%7}, {%8,%9}, {%0,%1,%2,%3};"
        : "+f"(d[0]), "+f"(d[1]), "+f"(d[2]), "+f"(d[3])
        : "r"(a[0]), "r"(a[1]), "r"(a[2]), "r"(a[3]), "r"(b[0]), "r"(b[1]));
}
__device__ __forceinline__ void bar_sync(int id) {
    asm volatile("bar.sync %0, 384;" :: "r"(id) : "memory");
}
__device__ __forceinline__ void bar_arrive(int id) {
    asm volatile("bar.arrive %0, 384;" :: "r"(id) : "memory");
}

// ================= prep: wproj -> tf32, dw weights -> packed =================
__global__ void se_prep(const float* __restrict__ wproj,
                        const float* __restrict__ wh1, const float* __restrict__ wh2,
                        const float* __restrict__ wv1, const float* __restrict__ wv2)
{
    int idx = blockIdx.x * 256 + threadIdx.x;   // 262144
    int k = idx & 31;
    int m = (idx >> 5) & 255;
    int c = idx >> 13;
    int br = k >> 3, lc = k & 7;
    float v = wproj[m * 1024 + br * 256 + c * 8 + lc];
    g_A_tf32[(c * 256 + m) * 32 + k] = f2tf32(v);

    if (blockIdx.x == 0) {
        for (int i = threadIdx.x; i < 9216; i += 256) {
            int ch = i / 36, r = i - ch * 36;
            int conv = r / 9, kk = r - conv * 9;
            const float* p = (conv == 0) ? wh1 : (conv == 1) ? wh2 : (conv == 2) ? wv1 : wv2;
            g_dw[(ch * 4 + conv) * 12 + kk] = p[ch * 9 + kk];
        }
    }
}

// ================= main: warp-specialized producer/consumer =================
// grid (2, HH, BB): blockIdx.x = half (N-half of the row)
__global__ __launch_bounds__(384, 1)
void se_main(const float* __restrict__ x, float* __restrict__ out)
{
    extern __shared__ char smc[];
    const uint32_t sb = smem_u32(smc);
    const int half = blockIdx.x, h = blockIdx.y, b = blockIdx.z;
    const int t = threadIdx.x, lane = t & 31;

    const float* xb = x + (long)b * 256 * HH * WW;

    if (t < 256) {
        // ================== CONSUMERS: 8 warps, MMA only ==================
        const int wid = t >> 5;
        const int wm = (wid & 3) * 64;       // M tile base
        const int wn = (wid >> 2) * 32;      // N tile base within 64-px half
        const int fr = lane >> 2, fq = lane & 3;
        const uint32_t aLane = (uint32_t)(((lane & 7) + ((lane >> 3) & 1) * 8) * 144 + ((lane >> 4) << 4));

        float acc[4][4][4];
        #pragma unroll
        for (int i = 0; i < 4; ++i)
            #pragma unroll
            for (int j = 0; j < 4; ++j)
                #pragma unroll
                for (int e = 0; e < 4; ++e) acc[i][j][e] = 0.f;

        uint32_t a[2][4][4];    // double-buffered A fragments
        uint32_t bf[2][4][2];   // double-buffered B fragments

        for (int c = 0; c < NCH; ++c) {
            const int s = c % NSTG;
            bar_sync(BFULL(s));

            const uint32_t abase = sb + AB_OFF + (uint32_t)(s * AB_SZ) + (uint32_t)(wm * 144) + aLane;
            const uint32_t* Yp = (const uint32_t*)(smc + YB_OFF + s * YB_SZ);

            // load kstep 0 fragments
            #pragma unroll
            for (int mt = 0; mt < 4; ++mt)
                ldsm4(a[0][mt], abase + (uint32_t)(mt * 16 * 144));
            #pragma unroll
            for (int nt = 0; nt < 4; ++nt) {
                const int col = wn + nt * 8 + fr;
                bf[0][nt][0] = Yp[fq * 68 + col];
                bf[0][nt][1] = Yp[(fq + 4) * 68 + col];
            }

            #pragma unroll
            for (int ks = 0; ks < 4; ++ks) {
                const int cur = ks & 1, nxt = cur ^ 1;
                if (ks < 3) {        // prefetch next kstep fragments
                    const int k0 = (ks + 1) * 8;
                    #pragma unroll
                    for (int mt = 0; mt < 4; ++mt)
                        ldsm4(a[nxt][mt], abase + (uint32_t)(mt * 16 * 144 + k0 * 4));
                    #pragma unroll
                    for (int nt = 0; nt < 4; ++nt) {
                        const int col = wn + nt * 8 + fr;
                        bf[nxt][nt][0] = Yp[(k0 + fq) * 68 + col];
                        bf[nxt][nt][1] = Yp[(k0 + fq + 4) * 68 + col];
                    }
                    if (ks == 2 && c + NSTG < NCH) bar_arrive(BEMPTY(s));   // all frags in regs
                }
                #pragma unroll
                for (int mt = 0; mt < 4; ++mt)
                    #pragma unroll
                    for (int nt = 0; nt < 4; ++nt)
                        mma_tf32(acc[mt][nt], a[cur][mt], &bf[cur][nt][0]);
            }
        }

        // ---- epilogue: ReLU + store (D fragment layout) ----
        const int g2 = lane >> 2, cq = lane & 3;
        #pragma unroll
        for (int mt = 0; mt < 4; ++mt) {
            const int o0 = wm + mt * 16 + g2;
            #pragma unroll
            for (int nt = 0; nt < 4; ++nt) {
                const int nn0 = half * 64 + wn + nt * 8 + cq * 2;
                float* p = out + (((long)(b * 256 + o0)) * HH + h) * WW + nn0;
                float2 v0, v1;
                v0.x = fmaxf(acc[mt][nt][0], 0.f);
                v0.y = fmaxf(acc[mt][nt][1], 0.f);
                v1.x = fmaxf(acc[mt][nt][2], 0.f);
                v1.y = fmaxf(acc[mt][nt][3], 0.f);
                *(float2*)p = v0;
                *(float2*)(p + 8L * HH * WW) = v1;
            }
        }
    } else {
        // ================== PRODUCERS: 4 warps, dw + A staging ==================
        const int pt = t - 256;                   // 0..127
        const int ng = pt & 15, ch = pt >> 4;     // pixel group, channel 0..7
        const int p0 = half * 64 + ng * 4;        // global pixel base (4 px)
        const int n0 = ng * 4;                    // local pixel base
        const float4 Z4 = make_float4(0.f, 0.f, 0.f, 0.f);

        float4 xh0, xh1, xh2, xv[8];

        auto loadx = [&](int c) {
            const float* xch = xb + (long)(c * 8 + ch) * HH * WW;
            const float* xr = xch + h * WW;
            xh0 = (p0 >= 4)      ? *(const float4*)(xr + p0 - 4) : Z4;
            xh1 =                  *(const float4*)(xr + p0);
            xh2 = (p0 + 7 < 128) ? *(const float4*)(xr + p0 + 4) : Z4;
            #pragma unroll
            for (int r = 0; r < 9; ++r) {
                if (r == 4) continue;
                const int hh = h + r - 4;
                const int i = (r < 4) ? r : r - 1;
                xv[i] = ((unsigned)hh < 128u) ? *(const float4*)(xch + hh * WW + p0) : Z4;
            }
        };

        loadx(0);

        for (int c = 0; c < NCH; ++c) {
            const int s = c % NSTG;
            if (c >= NSTG) bar_sync(BEMPTY(s));

            // A stage: 2048 float4 / 128 threads = 16 each
            #pragma unroll
            for (int i = 0; i < 16; ++i) {
                const int idx = pt + i * 128;
                const int m = idx >> 3, q = idx & 7;
                cpa16(sb + AB_OFF + (uint32_t)(s * AB_SZ + m * 144 + q * 16),
                      &g_A_tf32[(c * 256 + m) * 32 + q * 4]);
            }
            asm volatile("cp.async.commit_group;" ::: "memory");

            // ---- depthwise for chunk c from preloaded regs ----
            const int gch = c * 8 + ch;
            const float* wp = g_dw + gch * 48;
            uint32_t* Yw = (uint32_t*)(smc + YB_OFF + s * YB_SZ);

            {   // horizontal convs (wh1 -> k=ch, wh2 -> k=8+ch)
                float xvv[12];
                xvv[0] = xh0.x; xvv[1] = xh0.y; xvv[2]  = xh0.z; xvv[3]  = xh0.w;
                xvv[4] = xh1.x; xvv[5] = xh1.y; xvv[6]  = xh1.z; xvv[7]  = xh1.w;
                xvv[8] = xh2.x; xvv[9] = xh2.y; xvv[10] = xh2.z; xvv[11] = xh2.w;
                float a0 = 0.f, a1 = 0.f, a2 = 0.f, a3 = 0.f;
                float b0 = 0.f, b1 = 0.f, b2 = 0.f, b3 = 0.f;
                #pragma unroll
                for (int k = 0; k < 9; ++k) {
                    const float wa = wp[k], wb2 = wp[12 + k];
                    a0 = fmaf(wa, xvv[k],     a0); b0 = fmaf(wb2, xvv[k],     b0);
                    a1 = fmaf(wa, xvv[k + 1], a1); b1 = fmaf(wb2, xvv[k + 1], b1);
                    a2 = fmaf(wa, xvv[k + 2], a2); b2 = fmaf(wb2, xvv[k + 2], b2);
                    a3 = fmaf(wa, xvv[k + 3], a3); b3 = fmaf(wb2, xvv[k + 3], b3);
                }
                uint4 s0, s1;
                s0.x = f2tf32(a0); s0.y = f2tf32(a1); s0.z = f2tf32(a2); s0.w = f2tf32(a3);
                s1.x = f2tf32(b0); s1.y = f2tf32(b1); s1.z = f2tf32(b2); s1.w = f2tf32(b3);
                *(uint4*)(Yw + (ch)     * 68 + n0) = s0;
                *(uint4*)(Yw + (8 + ch) * 68 + n0) = s1;
            }
            {   // vertical convs (wv1 -> k=16+ch, wv2 -> k=24+ch)
                const float* wq = wp + 24;
                float a0 = 0.f, a1 = 0.f, a2 = 0.f, a3 = 0.f;
                float b0 = 0.f, b1 = 0.f, b2 = 0.f, b3 = 0.f;
                #pragma unroll
                for (int r = 0; r < 9; ++r) {
                    const float4 v = (r == 4) ? xh1 : xv[(r < 4) ? r : r - 1];
                    const float wa = wq[r], wb2 = wq[12 + r];
                    a0 = fmaf(wa, v.x, a0); b0 = fmaf(wb2, v.x, b0);
                    a1 = fmaf(wa, v.y, a1); b1 = fmaf(wb2, v.y, b1);
                    a2 = fmaf(wa, v.z, a2); b2 = fmaf(wb2, v.z, b2);
                    a3 = fmaf(wa, v.w, a3); b3 = fmaf(wb2, v.w, b3);
                }
                uint4 s0, s1;
                s0.x = f2tf32(a0); s0.y = f2tf32(a1); s0.z = f2tf32(a2); s0.w = f2tf32(a3);
                s1.x = f2tf32(b0); s1.y = f2tf32(b1); s1.z = f2tf32(b2); s1.w = f2tf32(b3);
                *(uint4*)(Yw + (16 + ch) * 68 + n0) = s0;
                *(uint4*)(Yw + (24 + ch) * 68 + n0) = s1;
            }

            // start x loads for next chunk (latency hides under ring slack)
            if (c + 1 < NCH) loadx(c + 1);

            asm volatile("cp.async.wait_group 0;" ::: "memory");
            bar_arrive(BFULL(s));
        }
    }
}

// ================= launch =================
extern "C" void kernel_launch(void* const* d_in, const int* in_sizes, int n_in,
                              void* d_out, int out_size)
{
    const float* x     = (const float*)d_in[0];
    const float* wh1   = (const float*)d_in[1];
    const float* wh2   = (const float*)d_in[2];
    const float* wv1   = (const float*)d_in[3];
    const float* wv2   = (const float*)d_in[4];
    const float* wproj = (const float*)d_in[5];
    float* out = (float*)d_out;

    se_prep<<<1024, 256>>>(wproj, wh1, wh2, wv1, wv2);

    cudaFuncSetAttribute(se_main, cudaFuncAttributeMaxDynamicSharedMemorySize, SMEM_BYTES);
    dim3 grid(2, HH, BB);
    se_main<<<grid, 384, SMEM_BYTES>>>(x, out);
}